// round 15
// baseline (speedup 1.0000x reference)
#include <cuda_runtime.h>
#include <math.h>

#define NN 50000
#define NE 800000
#define DD 64
#define NR 500
#define NT 1000

// ---- scratch (no allocs allowed) ----
__device__ float g_den[NN];
__device__ float g_agg[NN * DD];
__device__ float g_hatt[NN];
__device__ float g_tatt[NN];
__device__ float g_ratt[NR];
__device__ float g_tsatt[NT];
__device__ int2  g_eidx[NE];   // {src | ety<<16, eti | dst<<16}  (all fit 16b)

typedef unsigned long long ull;

__device__ __forceinline__ ull ffma2(ull a, ull b, ull c) {
    ull d;
    asm("fma.rn.f32x2 %0, %1, %2, %3;" : "=l"(d) : "l"(a), "l"(b), "l"(c));
    return d;
}
__device__ __forceinline__ ull dup2(float v) {
    ull r;
    asm("mov.b64 %0, {%1, %1};" : "=l"(r) : "f"(v));
    return r;
}
__device__ __forceinline__ float2 unpk(ull v) {
    float2 r;
    asm("mov.b64 {%0, %1}, %2;" : "=f"(r.x), "=f"(r.y) : "l"(v));
    return r;
}

// ---------------------------------------------------------------------------
// Fused: zero agg/den + pack edge indices (int4-vectorized) + per-row scalar
// attention projections (warp per row).   [R11's measured-best variant]
// ---------------------------------------------------------------------------
__global__ void k_scalar(const float* __restrict__ x,
                         const float* __restrict__ rel,
                         const float* __restrict__ tm,
                         const float* __restrict__ ah,
                         const float* __restrict__ at,
                         const float* __restrict__ ar,
                         const float* __restrict__ ats,
                         const int* __restrict__ src, const int* __restrict__ dst,
                         const int* __restrict__ ety, const int* __restrict__ eti) {
    int gtid = blockIdx.x * blockDim.x + threadIdx.x;
    int stride = gridDim.x * blockDim.x;

    float4* aggv = (float4*)g_agg;
    for (int j = gtid; j < NN * DD / 4; j += stride)
        aggv[j] = make_float4(0.f, 0.f, 0.f, 0.f);
    for (int j = gtid; j < NN; j += stride) g_den[j] = 0.f;

    {
        const int4* s4p = (const int4*)src;
        const int4* d4p = (const int4*)dst;
        const int4* r4p = (const int4*)ety;
        const int4* t4p = (const int4*)eti;
        int4* outp = (int4*)g_eidx;
        for (int j = gtid; j < NE / 4; j += stride) {
            int4 s4 = s4p[j], d4 = d4p[j], r4 = r4p[j], t4 = t4p[j];
            outp[j * 2 + 0] = make_int4(s4.x | (r4.x << 16), t4.x | (d4.x << 16),
                                        s4.y | (r4.y << 16), t4.y | (d4.y << 16));
            outp[j * 2 + 1] = make_int4(s4.z | (r4.z << 16), t4.z | (d4.z << 16),
                                        s4.w | (r4.w << 16), t4.w | (d4.w << 16));
        }
    }

    int w = gtid >> 5;
    int lane = threadIdx.x & 31;
    if (w < NN) {
        const float* row = x + (size_t)w * DD;
        float v0 = row[lane], v1 = row[lane + 32];
        float h = v0 * ah[lane] + v1 * ah[lane + 32];
        float t = v0 * at[lane] + v1 * at[lane + 32];
#pragma unroll
        for (int o = 16; o; o >>= 1) {
            h += __shfl_xor_sync(0xffffffffu, h, o);
            t += __shfl_xor_sync(0xffffffffu, t, o);
        }
        if (lane == 0) { g_hatt[w] = h; g_tatt[w] = t; }
    } else if (w < NN + NR) {
        int r = w - NN;
        const float* row = rel + (size_t)r * DD;
        float s = row[lane] * ar[lane] + row[lane + 32] * ar[lane + 32];
#pragma unroll
        for (int o = 16; o; o >>= 1) s += __shfl_xor_sync(0xffffffffu, s, o);
        if (lane == 0) g_ratt[r] = s;
    } else if (w < NN + NR + NT) {
        int t = w - NN - NR;
        const float* row = tm + (size_t)t * DD;
        float s = row[lane] * ats[lane] + row[lane + 32] * ats[lane + 32];
#pragma unroll
        for (int o = 16; o; o >>= 1) s += __shfl_xor_sync(0xffffffffu, s, o);
        if (lane == 0) g_tsatt[t] = s;
    }
}

// ---------------------------------------------------------------------------
// Fused edge pass: 8 threads/edge (at its L2 traffic floor — unchanged).
// ---------------------------------------------------------------------------
__global__ void k_edge(const float* __restrict__ x,
                       const float* __restrict__ rel,
                       const float* __restrict__ tm) {
    int gt = blockIdx.x * blockDim.x + threadIdx.x;
    int i = gt >> 3;
    if (i >= NE) return;
    int sub = gt & 7;
    int c = sub * 4;               // cols [c, c+4) and [c+32, c+36)

    int2 p = __ldg(&g_eidx[i]);    // group-broadcast
    int s = p.x & 0xFFFF;
    int r = ((unsigned)p.x) >> 16;
    int t = p.y & 0xFFFF;
    int d = ((unsigned)p.y) >> 16;

    float ex = 0.f;
    if (sub == 0) {
        float e = g_hatt[s] - g_tatt[d] + g_ratt[r] + g_tsatt[t];
        e = (e > 0.f) ? e : 0.1f * e;
        ex = __expf(e);
        atomicAdd(&g_den[d], ex);
    }
    ex = __shfl_sync(0xffffffffu, ex, (threadIdx.x & 31) & ~7);

    const float* xr = x   + (size_t)s * DD;
    const float* rr = rel + (size_t)r * DD;
    const float* tr = tm  + (size_t)t * DD;

    float4 x0 = *(const float4*)(xr + c);
    float4 x1 = *(const float4*)(xr + c + 32);
    float4 t0 = *(const float4*)(tr + c);
    float4 t1 = *(const float4*)(tr + c + 32);
    float4 r0 = *(const float4*)(rr + c);
    float4 r1 = *(const float4*)(rr + c + 32);

    float4 o0, o1;
    o0.x = (x0.x + t0.x) * (r0.x + t0.x) * ex;
    o0.y = (x0.y + t0.y) * (r0.y + t0.y) * ex;
    o0.z = (x0.z + t0.z) * (r0.z + t0.z) * ex;
    o0.w = (x0.w + t0.w) * (r0.w + t0.w) * ex;
    o1.x = (x1.x + t1.x) * (r1.x + t1.x) * ex;
    o1.y = (x1.y + t1.y) * (r1.y + t1.y) * ex;
    o1.z = (x1.z + t1.z) * (r1.z + t1.z) * ex;
    o1.w = (x1.w + t1.w) * (r1.w + t1.w) * ex;

    float* pd = &g_agg[(size_t)d * DD + c];
    asm volatile("red.global.add.v4.f32 [%0], {%1,%2,%3,%4};"
                 :: "l"(pd), "f"(o0.x), "f"(o0.y), "f"(o0.z), "f"(o0.w)
                 : "memory");
    asm volatile("red.global.add.v4.f32 [%0], {%1,%2,%3,%4};"
                 :: "l"(pd + 32), "f"(o1.x), "f"(o1.y), "f"(o1.z), "f"(o1.w)
                 : "memory");
}

// ---------------------------------------------------------------------------
// Fused GEMM — exact R10 configuration (the 91.1us best), rel path included:
//   blocks [0,NBX):    x_out = (agg/den) @ trans_w + x @ loop_w
//   blocks [NBX,+NBR): rel_out = rel_repr @ w_rel   (8 rows per 512-thr block)
// ---------------------------------------------------------------------------
#define GROWS 128
#define GTHREADS 512
#define NBX ((NN + GROWS - 1) / GROWS)     // 391
#define NBR ((NR + 7) / 8)                 // 63
#define ATSTR 130                          // 128 rows + 2 pad (pair-aligned)
#define OFF_WL 4096
#define OFF_AT 8192
#define OFF_XT (8192 + DD * ATSTR)
#define SMEM_FLOATS (8192 + 2 * DD * ATSTR)
#define SMEM_BYTES (SMEM_FLOATS * 4)

__global__ void k_gemm(const float* __restrict__ x,
                       const float* __restrict__ wt,
                       const float* __restrict__ wl,
                       const float* __restrict__ rel,
                       const float* __restrict__ wr,
                       float* __restrict__ out,
                       float* __restrict__ out_r) {
    extern __shared__ __align__(16) float sm[];
    float* sWt = sm;
    float* sWl = sm + OFF_WL;
    float* sAT = sm + OFF_AT;
    float* sXT = sm + OFF_XT;

    int tid = threadIdx.x;

    if (blockIdx.x >= NBX) {
        // ---- rel path: 8 rows per block (reuses sm as staging) ----
        float(*sR)[DD] = (float(*)[DD])sm;
        int j = tid & 63, ry = tid >> 6;           // ry 0..7
        int r0 = (blockIdx.x - NBX) * 8;
        int grow = r0 + ry;
        sR[ry][j] = (grow < NR) ? rel[(size_t)grow * DD + j] : 0.f;
        __syncthreads();
        float acc = 0.f;
#pragma unroll 8
        for (int k = 0; k < DD; k++) acc += sR[ry][k] * __ldg(&wr[k * DD + j]);
        if (grow < NR) out_r[(size_t)grow * DD + j] = acc;
        return;
    }

    for (int j = tid; j < DD * DD; j += GTHREADS) { sWt[j] = wt[j]; sWl[j] = wl[j]; }

    int row0 = blockIdx.x * GROWS;
    {
        int r = tid >> 4;                 // 0..31
        int c4 = (tid & 15) * 4;
        for (int rr = r; rr < GROWS; rr += 32) {
            int grow = row0 + rr;
            float4 a = make_float4(0.f, 0.f, 0.f, 0.f);
            float4 b = make_float4(0.f, 0.f, 0.f, 0.f);
            if (grow < NN) {
                float dn = __ldg(&g_den[grow]);
                float inv = (dn > 0.f) ? __fdividef(1.f, dn) : 0.f;
                a = *(const float4*)&g_agg[(size_t)grow * DD + c4];
                a.x *= inv; a.y *= inv; a.z *= inv; a.w *= inv;
                b = *(const float4*)(x + (size_t)grow * DD + c4);
            }
            sAT[(c4 + 0) * ATSTR + rr] = a.x;
            sAT[(c4 + 1) * ATSTR + rr] = a.y;
            sAT[(c4 + 2) * ATSTR + rr] = a.z;
            sAT[(c4 + 3) * ATSTR + rr] = a.w;
            sXT[(c4 + 0) * ATSTR + rr] = b.x;
            sXT[(c4 + 1) * ATSTR + rr] = b.y;
            sXT[(c4 + 2) * ATSTR + rr] = b.z;
            sXT[(c4 + 3) * ATSTR + rr] = b.w;
        }
    }
    __syncthreads();

    int tx = tid & 15;   // column group (4 output cols)
    int ty = tid >> 4;   // row group    (4 output rows), 0..31

    ull acc[4][2];       // [col][row-pair]
#pragma unroll
    for (int c0 = 0; c0 < 4; c0++) { acc[c0][0] = 0ull; acc[c0][1] = 0ull; }

    // software pipeline: prefetch k+1 while FMAing k
    float4 w0 = *(const float4*)&sWt[tx * 4];
    float4 w1 = *(const float4*)&sWl[tx * 4];
    ull a01 = *(const ull*)&sAT[ty * 4];
    ull a23 = *(const ull*)&sAT[ty * 4 + 2];
    ull b01 = *(const ull*)&sXT[ty * 4];
    ull b23 = *(const ull*)&sXT[ty * 4 + 2];

#pragma unroll 4
    for (int k = 0; k < DD; k++) {
        float4 nw0, nw1;
        ull na01, na23, nb01, nb23;
        int kn = k + 1;
        if (kn < DD) {
            nw0  = *(const float4*)&sWt[kn * DD + tx * 4];
            nw1  = *(const float4*)&sWl[kn * DD + tx * 4];
            na01 = *(const ull*)&sAT[kn * ATSTR + ty * 4];
            na23 = *(const ull*)&sAT[kn * ATSTR + ty * 4 + 2];
            nb01 = *(const ull*)&sXT[kn * ATSTR + ty * 4];
            nb23 = *(const ull*)&sXT[kn * ATSTR + ty * 4 + 2];
        }
        ull dd;
        dd = dup2(w0.x); acc[0][0] = ffma2(a01, dd, acc[0][0]); acc[0][1] = ffma2(a23, dd, acc[0][1]);
        dd = dup2(w0.y); acc[1][0] = ffma2(a01, dd, acc[1][0]); acc[1][1] = ffma2(a23, dd, acc[1][1]);
        dd = dup2(w0.z); acc[2][0] = ffma2(a01, dd, acc[2][0]); acc[2][1] = ffma2(a23, dd, acc[2][1]);
        dd = dup2(w0.w); acc[3][0] = ffma2(a01, dd, acc[3][0]); acc[3][1] = ffma2(a23, dd, acc[3][1]);
        dd = dup2(w1.x); acc[0][0] = ffma2(b01, dd, acc[0][0]); acc[0][1] = ffma2(b23, dd, acc[0][1]);
        dd = dup2(w1.y); acc[1][0] = ffma2(b01, dd, acc[1][0]); acc[1][1] = ffma2(b23, dd, acc[1][1]);
        dd = dup2(w1.z); acc[2][0] = ffma2(b01, dd, acc[2][0]); acc[2][1] = ffma2(b23, dd, acc[2][1]);
        dd = dup2(w1.w); acc[3][0] = ffma2(b01, dd, acc[3][0]); acc[3][1] = ffma2(b23, dd, acc[3][1]);
        w0 = nw0; w1 = nw1;
        a01 = na01; a23 = na23; b01 = nb01; b23 = nb23;
    }

#pragma unroll
    for (int p = 0; p < 2; p++) {
        float2 u0 = unpk(acc[0][p]);
        float2 u1 = unpk(acc[1][p]);
        float2 u2 = unpk(acc[2][p]);
        float2 u3 = unpk(acc[3][p]);
        int rlo = row0 + ty * 4 + p * 2;
        if (rlo < NN)
            *(float4*)(out + (size_t)rlo * DD + tx * 4) =
                make_float4(u0.x, u1.x, u2.x, u3.x);
        if (rlo + 1 < NN)
            *(float4*)(out + (size_t)(rlo + 1) * DD + tx * 4) =
                make_float4(u0.y, u1.y, u2.y, u3.y);
    }
}

// ---------------------------------------------------------------------------
extern "C" void kernel_launch(void* const* d_in, const int* in_sizes, int n_in,
                              void* d_out, int out_size) {
    const float* x       = (const float*)d_in[0];
    const float* rel     = (const float*)d_in[1];
    const float* tm      = (const float*)d_in[2];
    const int*   src     = (const int*)d_in[3];
    const int*   dst     = (const int*)d_in[4];
    const int*   ety     = (const int*)d_in[5];
    const int*   eti     = (const int*)d_in[6];
    const float* trans_w = (const float*)d_in[7];
    const float* loop_w  = (const float*)d_in[8];
    const float* w_rel   = (const float*)d_in[9];
    const float* ah      = (const float*)d_in[10];
    const float* at      = (const float*)d_in[11];
    const float* ar      = (const float*)d_in[12];
    const float* ats     = (const float*)d_in[13];

    float* out   = (float*)d_out;            // x_out  [50000*64]
    float* out_r = out + (size_t)NN * DD;    // rel_out [500*64]

    cudaFuncSetAttribute(k_gemm, cudaFuncAttributeMaxDynamicSharedMemorySize,
                         SMEM_BYTES);

    {
        int warps = NN + NR + NT;
        int blocks = (warps * 32 + 255) / 256;
        k_scalar<<<blocks, 256>>>(x, rel, tm, ah, at, ar, ats, src, dst, ety, eti);
    }

    {
        long long threads = (long long)NE * 8;
        int blocks = (int)((threads + 255) / 256);
        k_edge<<<blocks, 256>>>(x, rel, tm);
    }

    k_gemm<<<NBX + NBR, GTHREADS, SMEM_BYTES>>>(x, trans_w, loop_w, rel, w_rel,
                                                out, out_r);

    (void)in_sizes; (void)n_in; (void)out_size;
}

// round 16
// speedup vs baseline: 1.5905x; 1.5905x over previous
#include <cuda_runtime.h>
#include <math.h>

#define NN 50000
#define NE 800000
#define DD 64
#define NR 500
#define NT 1000

// ---- scratch (no allocs allowed) ----
__device__ float g_den[NN];
__device__ float g_agg[NN * DD];
__device__ float g_hatt[NN];
__device__ float g_tatt[NN];
__device__ float g_ratt[NR];
__device__ float g_tsatt[NT];
__device__ int2  g_eidx[NE];   // {src | ety<<16, eti | dst<<16}  (all fit 16b)

typedef unsigned long long ull;

__device__ __forceinline__ ull ffma2(ull a, ull b, ull c) {
    ull d;
    asm("fma.rn.f32x2 %0, %1, %2, %3;" : "=l"(d) : "l"(a), "l"(b), "l"(c));
    return d;
}
__device__ __forceinline__ ull dup2(float v) {
    ull r;
    asm("mov.b64 %0, {%1, %1};" : "=l"(r) : "f"(v));
    return r;
}
__device__ __forceinline__ float2 unpk(ull v) {
    float2 r;
    asm("mov.b64 {%0, %1}, %2;" : "=f"(r.x), "=f"(r.y) : "l"(v));
    return r;
}

// ---------------------------------------------------------------------------
// Fused: zero agg/den + pack edge indices (int4-vectorized) + per-row scalar
// attention projections (warp per row).
// ---------------------------------------------------------------------------
__global__ void k_scalar(const float* __restrict__ x,
                         const float* __restrict__ rel,
                         const float* __restrict__ tm,
                         const float* __restrict__ ah,
                         const float* __restrict__ at,
                         const float* __restrict__ ar,
                         const float* __restrict__ ats,
                         const int* __restrict__ src, const int* __restrict__ dst,
                         const int* __restrict__ ety, const int* __restrict__ eti) {
    int gtid = blockIdx.x * blockDim.x + threadIdx.x;
    int stride = gridDim.x * blockDim.x;

    float4* aggv = (float4*)g_agg;
    for (int j = gtid; j < NN * DD / 4; j += stride)
        aggv[j] = make_float4(0.f, 0.f, 0.f, 0.f);
    for (int j = gtid; j < NN; j += stride) g_den[j] = 0.f;

    {
        const int4* s4p = (const int4*)src;
        const int4* d4p = (const int4*)dst;
        const int4* r4p = (const int4*)ety;
        const int4* t4p = (const int4*)eti;
        int4* outp = (int4*)g_eidx;
        for (int j = gtid; j < NE / 4; j += stride) {
            int4 s4 = s4p[j], d4 = d4p[j], r4 = r4p[j], t4 = t4p[j];
            outp[j * 2 + 0] = make_int4(s4.x | (r4.x << 16), t4.x | (d4.x << 16),
                                        s4.y | (r4.y << 16), t4.y | (d4.y << 16));
            outp[j * 2 + 1] = make_int4(s4.z | (r4.z << 16), t4.z | (d4.z << 16),
                                        s4.w | (r4.w << 16), t4.w | (d4.w << 16));
        }
    }

    int w = gtid >> 5;
    int lane = threadIdx.x & 31;
    if (w < NN) {
        const float* row = x + (size_t)w * DD;
        float v0 = row[lane], v1 = row[lane + 32];
        float h = v0 * ah[lane] + v1 * ah[lane + 32];
        float t = v0 * at[lane] + v1 * at[lane + 32];
#pragma unroll
        for (int o = 16; o; o >>= 1) {
            h += __shfl_xor_sync(0xffffffffu, h, o);
            t += __shfl_xor_sync(0xffffffffu, t, o);
        }
        if (lane == 0) { g_hatt[w] = h; g_tatt[w] = t; }
    } else if (w < NN + NR) {
        int r = w - NN;
        const float* row = rel + (size_t)r * DD;
        float s = row[lane] * ar[lane] + row[lane + 32] * ar[lane + 32];
#pragma unroll
        for (int o = 16; o; o >>= 1) s += __shfl_xor_sync(0xffffffffu, s, o);
        if (lane == 0) g_ratt[r] = s;
    } else if (w < NN + NR + NT) {
        int t = w - NN - NR;
        const float* row = tm + (size_t)t * DD;
        float s = row[lane] * ats[lane] + row[lane + 32] * ats[lane + 32];
#pragma unroll
        for (int o = 16; o; o >>= 1) s += __shfl_xor_sync(0xffffffffu, s, o);
        if (lane == 0) g_tsatt[t] = s;
    }
}

// ---------------------------------------------------------------------------
// Fused edge pass: 8 threads/edge (at its L2 traffic floor).
// Leader lane: ex = exp(leaky_relu(logit)); den[dst] += ex; broadcast ex.
// All lanes: RED the UNNORMALIZED message ex*(x[src]+t)*(rel+t) into agg[dst].
// ---------------------------------------------------------------------------
__global__ void k_edge(const float* __restrict__ x,
                       const float* __restrict__ rel,
                       const float* __restrict__ tm) {
    int gt = blockIdx.x * blockDim.x + threadIdx.x;
    int i = gt >> 3;
    if (i >= NE) return;
    int sub = gt & 7;
    int c = sub * 4;               // cols [c, c+4) and [c+32, c+36)

    int2 p = __ldg(&g_eidx[i]);    // group-broadcast
    int s = p.x & 0xFFFF;
    int r = ((unsigned)p.x) >> 16;
    int t = p.y & 0xFFFF;
    int d = ((unsigned)p.y) >> 16;

    float ex = 0.f;
    if (sub == 0) {
        float e = g_hatt[s] - g_tatt[d] + g_ratt[r] + g_tsatt[t];
        e = (e > 0.f) ? e : 0.1f * e;
        ex = __expf(e);
        atomicAdd(&g_den[d], ex);
    }
    ex = __shfl_sync(0xffffffffu, ex, (threadIdx.x & 31) & ~7);

    const float* xr = x   + (size_t)s * DD;
    const float* rr = rel + (size_t)r * DD;
    const float* tr = tm  + (size_t)t * DD;

    float4 x0 = *(const float4*)(xr + c);
    float4 x1 = *(const float4*)(xr + c + 32);
    float4 t0 = *(const float4*)(tr + c);
    float4 t1 = *(const float4*)(tr + c + 32);
    float4 r0 = *(const float4*)(rr + c);
    float4 r1 = *(const float4*)(rr + c + 32);

    float4 o0, o1;
    o0.x = (x0.x + t0.x) * (r0.x + t0.x) * ex;
    o0.y = (x0.y + t0.y) * (r0.y + t0.y) * ex;
    o0.z = (x0.z + t0.z) * (r0.z + t0.z) * ex;
    o0.w = (x0.w + t0.w) * (r0.w + t0.w) * ex;
    o1.x = (x1.x + t1.x) * (r1.x + t1.x) * ex;
    o1.y = (x1.y + t1.y) * (r1.y + t1.y) * ex;
    o1.z = (x1.z + t1.z) * (r1.z + t1.z) * ex;
    o1.w = (x1.w + t1.w) * (r1.w + t1.w) * ex;

    float* pd = &g_agg[(size_t)d * DD + c];
    asm volatile("red.global.add.v4.f32 [%0], {%1,%2,%3,%4};"
                 :: "l"(pd), "f"(o0.x), "f"(o0.y), "f"(o0.z), "f"(o0.w)
                 : "memory");
    asm volatile("red.global.add.v4.f32 [%0], {%1,%2,%3,%4};"
                 :: "l"(pd + 32), "f"(o1.x), "f"(o1.y), "f"(o1.z), "f"(o1.w)
                 : "memory");
}

// ---------------------------------------------------------------------------
// Fused GEMM — R10 configuration, rel path included:
//   blocks [0,NBX):    x_out = (agg/den) @ trans_w + x @ loop_w
//   blocks [NBX,+NBR): rel_out = rel_repr @ w_rel   (8 rows per 512-thr block)
// ---------------------------------------------------------------------------
#define GROWS 128
#define GTHREADS 512
#define NBX ((NN + GROWS - 1) / GROWS)     // 391
#define NBR ((NR + 7) / 8)                 // 63
#define ATSTR 130                          // 128 rows + 2 pad (pair-aligned)
#define OFF_WL 4096
#define OFF_AT 8192
#define OFF_XT (8192 + DD * ATSTR)
#define SMEM_FLOATS (8192 + 2 * DD * ATSTR)
#define SMEM_BYTES (SMEM_FLOATS * 4)

__global__ void k_gemm(const float* __restrict__ x,
                       const float* __restrict__ wt,
                       const float* __restrict__ wl,
                       const float* __restrict__ rel,
                       const float* __restrict__ wr,
                       float* __restrict__ out,
                       float* __restrict__ out_r) {
    extern __shared__ __align__(16) float sm[];
    float* sWt = sm;
    float* sWl = sm + OFF_WL;
    float* sAT = sm + OFF_AT;
    float* sXT = sm + OFF_XT;

    int tid = threadIdx.x;

    if (blockIdx.x >= NBX) {
        // ---- rel path: 8 rows per block (reuses sm as staging) ----
        float(*sR)[DD] = (float(*)[DD])sm;
        int j = tid & 63, ry = tid >> 6;           // ry 0..7
        int r0 = (blockIdx.x - NBX) * 8;
        int grow = r0 + ry;
        sR[ry][j] = (grow < NR) ? rel[(size_t)grow * DD + j] : 0.f;
        __syncthreads();
        float acc = 0.f;
#pragma unroll 8
        for (int k = 0; k < DD; k++) acc += sR[ry][k] * __ldg(&wr[k * DD + j]);
        if (grow < NR) out_r[(size_t)grow * DD + j] = acc;
        return;
    }

    for (int j = tid; j < DD * DD; j += GTHREADS) { sWt[j] = wt[j]; sWl[j] = wl[j]; }

    int row0 = blockIdx.x * GROWS;
    {
        int r = tid >> 4;                 // 0..31
        int c4 = (tid & 15) * 4;
        for (int rr = r; rr < GROWS; rr += 32) {
            int grow = row0 + rr;
            float4 a = make_float4(0.f, 0.f, 0.f, 0.f);
            float4 b = make_float4(0.f, 0.f, 0.f, 0.f);
            if (grow < NN) {
                float dn = __ldg(&g_den[grow]);
                float inv = (dn > 0.f) ? __fdividef(1.f, dn) : 0.f;
                a = *(const float4*)&g_agg[(size_t)grow * DD + c4];
                a.x *= inv; a.y *= inv; a.z *= inv; a.w *= inv;
                b = *(const float4*)(x + (size_t)grow * DD + c4);
            }
            sAT[(c4 + 0) * ATSTR + rr] = a.x;
            sAT[(c4 + 1) * ATSTR + rr] = a.y;
            sAT[(c4 + 2) * ATSTR + rr] = a.z;
            sAT[(c4 + 3) * ATSTR + rr] = a.w;
            sXT[(c4 + 0) * ATSTR + rr] = b.x;
            sXT[(c4 + 1) * ATSTR + rr] = b.y;
            sXT[(c4 + 2) * ATSTR + rr] = b.z;
            sXT[(c4 + 3) * ATSTR + rr] = b.w;
        }
    }
    __syncthreads();

    int tx = tid & 15;   // column group (4 output cols)
    int ty = tid >> 4;   // row group    (4 output rows), 0..31

    ull acc[4][2];       // [col][row-pair]
#pragma unroll
    for (int c0 = 0; c0 < 4; c0++) { acc[c0][0] = 0ull; acc[c0][1] = 0ull; }

    // software pipeline: prefetch k+1 while FMAing k
    float4 w0 = *(const float4*)&sWt[tx * 4];
    float4 w1 = *(const float4*)&sWl[tx * 4];
    ull a01 = *(const ull*)&sAT[ty * 4];
    ull a23 = *(const ull*)&sAT[ty * 4 + 2];
    ull b01 = *(const ull*)&sXT[ty * 4];
    ull b23 = *(const ull*)&sXT[ty * 4 + 2];

#pragma unroll 4
    for (int k = 0; k < DD; k++) {
        float4 nw0, nw1;
        ull na01, na23, nb01, nb23;
        int kn = k + 1;
        if (kn < DD) {
            nw0  = *(const float4*)&sWt[kn * DD + tx * 4];
            nw1  = *(const float4*)&sWl[kn * DD + tx * 4];
            na01 = *(const ull*)&sAT[kn * ATSTR + ty * 4];
            na23 = *(const ull*)&sAT[kn * ATSTR + ty * 4 + 2];
            nb01 = *(const ull*)&sXT[kn * ATSTR + ty * 4];
            nb23 = *(const ull*)&sXT[kn * ATSTR + ty * 4 + 2];
        }
        ull dd;
        dd = dup2(w0.x); acc[0][0] = ffma2(a01, dd, acc[0][0]); acc[0][1] = ffma2(a23, dd, acc[0][1]);
        dd = dup2(w0.y); acc[1][0] = ffma2(a01, dd, acc[1][0]); acc[1][1] = ffma2(a23, dd, acc[1][1]);
        dd = dup2(w0.z); acc[2][0] = ffma2(a01, dd, acc[2][0]); acc[2][1] = ffma2(a23, dd, acc[2][1]);
        dd = dup2(w0.w); acc[3][0] = ffma2(a01, dd, acc[3][0]); acc[3][1] = ffma2(a23, dd, acc[3][1]);
        dd = dup2(w1.x); acc[0][0] = ffma2(b01, dd, acc[0][0]); acc[0][1] = ffma2(b23, dd, acc[0][1]);
        dd = dup2(w1.y); acc[1][0] = ffma2(b01, dd, acc[1][0]); acc[1][1] = ffma2(b23, dd, acc[1][1]);
        dd = dup2(w1.z); acc[2][0] = ffma2(b01, dd, acc[2][0]); acc[2][1] = ffma2(b23, dd, acc[2][1]);
        dd = dup2(w1.w); acc[3][0] = ffma2(b01, dd, acc[3][0]); acc[3][1] = ffma2(b23, dd, acc[3][1]);
        w0 = nw0; w1 = nw1;
        a01 = na01; a23 = na23; b01 = nb01; b23 = nb23;
    }

#pragma unroll
    for (int p = 0; p < 2; p++) {
        float2 u0 = unpk(acc[0][p]);
        float2 u1 = unpk(acc[1][p]);
        float2 u2 = unpk(acc[2][p]);
        float2 u3 = unpk(acc[3][p]);
        int rlo = row0 + ty * 4 + p * 2;
        if (rlo < NN)
            *(float4*)(out + (size_t)rlo * DD + tx * 4) =
                make_float4(u0.x, u1.x, u2.x, u3.x);
        if (rlo + 1 < NN)
            *(float4*)(out + (size_t)(rlo + 1) * DD + tx * 4) =
                make_float4(u0.y, u1.y, u2.y, u3.y);
    }
}

// ---------------------------------------------------------------------------
extern "C" void kernel_launch(void* const* d_in, const int* in_sizes, int n_in,
                              void* d_out, int out_size) {
    const float* x       = (const float*)d_in[0];
    const float* rel     = (const float*)d_in[1];
    const float* tm      = (const float*)d_in[2];
    const int*   src     = (const int*)d_in[3];
    const int*   dst     = (const int*)d_in[4];
    const int*   ety     = (const int*)d_in[5];
    const int*   eti     = (const int*)d_in[6];
    const float* trans_w = (const float*)d_in[7];
    const float* loop_w  = (const float*)d_in[8];
    const float* w_rel   = (const float*)d_in[9];
    const float* ah      = (const float*)d_in[10];
    const float* at      = (const float*)d_in[11];
    const float* ar      = (const float*)d_in[12];
    const float* ats     = (const float*)d_in[13];

    float* out   = (float*)d_out;            // x_out  [50000*64]
    float* out_r = out + (size_t)NN * DD;    // rel_out [500*64]

    cudaFuncSetAttribute(k_gemm, cudaFuncAttributeMaxDynamicSharedMemorySize,
                         SMEM_BYTES);

    {
        int warps = NN + NR + NT;
        int blocks = (warps * 32 + 255) / 256;
        k_scalar<<<blocks, 256>>>(x, rel, tm, ah, at, ar, ats, src, dst, ety, eti);
    }

    {
        long long threads = (long long)NE * 8;
        int blocks = (int)((threads + 255) / 256);
        k_edge<<<blocks, 256>>>(x, rel, tm);
    }

    k_gemm<<<NBX + NBR, GTHREADS, SMEM_BYTES>>>(x, trans_w, loop_w, rel, w_rel,
                                                out, out_r);

    (void)in_sizes; (void)n_in; (void)out_size;
}